// round 2
// baseline (speedup 1.0000x reference)
#include <cuda_runtime.h>

#define B_ 4
#define C_ 3
#define H_ 360
#define W_ 640
#define HP 364
#define WP 644
#define GH 52
#define GW 92
#define BP (B_*GH*GW)   /* 19136 patches */
#define FH 64           /* F_HEAD */
#define FC 32           /* F_CH  */
#define NF 64           /* N_FEATS */

// ---------------- scratch (device globals; no allocation allowed) ----------
__device__ float g_feat1[BP*FH*25];        // conv1 out: [p][64][5x5]
__device__ float g_feat2[BP*FH*9];         // conv2 out: [p][64][3x3]
__device__ float g_kern [BP*FC*27];        // per-patch kernels [p][864]
__device__ float g_bias [BP*FC];           // per-patch bias [p][32]
__device__ float g_ymid [B_*FC*HP*WP];     // adaptive conv out
__device__ float g_y3  [(size_t)B_*NF*HP*WP]; // conv3 out

__device__ __forceinline__ float rgb_mean(int c) {
    return (c == 0) ? 0.4488f*255.0f : (c == 1) ? 0.4371f*255.0f : 0.404f*255.0f;
}

// ---------------- K1: patch extract (+mean sub, zero pad) + conv1 3x3 VALID + relu
__global__ void k1_conv1(const float* __restrict__ x, const float* __restrict__ w1,
                         const float* __restrict__ b1) {
    __shared__ float sp[C_*49];
    __shared__ float ws[FH*27];
    __shared__ float bs[FH];
    int p = blockIdx.x;
    int b = p / (GH*GW);
    int r = p % (GH*GW);
    int gi = r / GW, gj = r % GW;
    int tid = threadIdx.x;
    if (tid < C_*49) {
        int c = tid/49, q = tid%49;
        int i = q/7, j = q%7;
        int h = gi*7 + i, w = gj*7 + j;
        float v = 0.f;
        if (h < H_ && w < W_) v = x[((b*C_+c)*H_ + h)*W_ + w] - rgb_mean(c);
        sp[tid] = v;
    }
    for (int idx = tid; idx < FH*27; idx += blockDim.x) ws[idx] = w1[idx];
    if (tid < FH) bs[tid] = b1[tid];
    __syncthreads();
    for (int idx = tid; idx < FH*25; idx += blockDim.x) {
        int oc = idx / 25, q = idx % 25;
        int oy = q/5, ox = q%5;
        float acc = bs[oc];
        #pragma unroll
        for (int c = 0; c < 3; c++)
            #pragma unroll
            for (int ky = 0; ky < 3; ky++)
                #pragma unroll
                for (int kx = 0; kx < 3; kx++)
                    acc += sp[c*49 + (oy+ky)*7 + (ox+kx)] * ws[oc*27 + c*9 + ky*3 + kx];
        g_feat1[p*(FH*25) + idx] = fmaxf(acc, 0.f);
    }
}

// ---------------- K2: conv2 3x3 VALID (64->64) + relu. One thread per output.
__global__ void k2_conv2(const float* __restrict__ w2, const float* __restrict__ b2) {
    __shared__ float f1[FH*25];
    int p = blockIdx.x;
    int tid = threadIdx.x;  // 576 threads
    for (int idx = tid; idx < FH*25; idx += blockDim.x) f1[idx] = g_feat1[p*(FH*25)+idx];
    __syncthreads();
    int oc = tid/9, q = tid%9;
    int oy = q/3, ox = q%3;
    float acc = b2[oc];
    const float* wr = w2 + oc*(FH*9);
    #pragma unroll 8
    for (int ic = 0; ic < FH; ic++) {
        const float* fp = f1 + ic*25 + oy*5 + ox;
        const float* wp = wr + ic*9;
        acc += fp[0]*wp[0] + fp[1]*wp[1] + fp[2]*wp[2]
             + fp[5]*wp[3] + fp[6]*wp[4] + fp[7]*wp[5]
             + fp[10]*wp[6] + fp[11]*wp[7] + fp[12]*wp[8];
    }
    g_feat2[p*(FH*9) + tid] = fmaxf(acc, 0.f);
}

// ---------------- K3: GEMM  C[M=BP][N] = g_feat2[M][576] * Bw[N][576]^T + bias[N]
__global__ void k3_gemm(const float* __restrict__ Bw, const float* __restrict__ bias,
                        int N, int which /* 0 -> g_kern, 1 -> g_bias */) {
    const int K = FH*9;  // 576
    __shared__ float As[16][129];
    __shared__ float Bs[16][65];
    int tid = threadIdx.x;
    int m0 = blockIdx.y*128, n0 = blockIdx.x*64;
    int ty = tid/16, tx = tid%16;
    float acc[8][4];
    #pragma unroll
    for (int i=0;i<8;i++)
        #pragma unroll
        for (int j=0;j<4;j++) acc[i][j]=0.f;
    for (int k0 = 0; k0 < K; k0 += 16) {
        #pragma unroll
        for (int i=0;i<8;i++){
            int idx = tid + i*256;
            int kk = idx & 15, mm = idx >> 4;
            int m = m0 + mm;
            As[kk][mm] = (m < BP) ? g_feat2[m*K + k0 + kk] : 0.f;
        }
        #pragma unroll
        for (int i=0;i<4;i++){
            int idx = tid + i*256;
            int kk = idx & 15, nn = idx >> 4;
            int n = n0 + nn;
            Bs[kk][nn] = (n < N) ? Bw[n*K + k0 + kk] : 0.f;
        }
        __syncthreads();
        #pragma unroll
        for (int kk=0;kk<16;kk++){
            float a[8], bb2[4];
            #pragma unroll
            for (int i=0;i<8;i++) a[i]=As[kk][ty*8+i];
            #pragma unroll
            for (int j=0;j<4;j++) bb2[j]=Bs[kk][tx*4+j];
            #pragma unroll
            for (int i=0;i<8;i++)
                #pragma unroll
                for (int j=0;j<4;j++) acc[i][j] += a[i]*bb2[j];
        }
        __syncthreads();
    }
    float* Cout = which ? g_bias : g_kern;
    #pragma unroll
    for (int i=0;i<8;i++){
        int m = m0 + ty*8 + i;
        if (m >= BP) continue;
        #pragma unroll
        for (int j=0;j<4;j++){
            int n = n0 + tx*4 + j;
            if (n < N) Cout[m*N + n] = acc[i][j] + bias[n];
        }
    }
}

// ---------------- K4: adaptive per-patch 3x3 conv (27 taps, per-patch zero pad)
// 128 threads: strided loads cover all 147 patch elements (round-1 bug: 64 threads
// with `if (tid<147)` guard left channels 1-2 as zeros).
__global__ void k4_adapt(const float* __restrict__ x) {
    __shared__ float ks[FC*27];
    __shared__ float bs[FC];
    __shared__ float xs[C_*81];   // 3 x 9 x 9, zero-padded patch
    int p = blockIdx.x;
    int b = p/(GH*GW); int r = p%(GH*GW);
    int gi = r/GW, gj = r%GW;
    int tid = threadIdx.x;  // 128
    for (int idx = tid; idx < FC*27; idx += blockDim.x) ks[idx] = g_kern[p*(FC*27)+idx];
    if (tid < FC) bs[tid] = g_bias[p*FC+tid];
    for (int idx = tid; idx < C_*81; idx += blockDim.x) xs[idx] = 0.f;
    __syncthreads();
    for (int idx = tid; idx < C_*49; idx += blockDim.x) {
        int c = idx/49, q = idx%49, i = q/7, j = q%7;
        int h = gi*7+i, w = gj*7+j;
        float v = 0.f;
        if (h < H_ && w < W_) v = x[((b*C_+c)*H_+h)*W_+w] - rgb_mean(c);
        xs[c*81 + (i+1)*9 + (j+1)] = v;
    }
    __syncthreads();
    if (tid < 49) {
        int i = tid/7, j = tid%7;
        float v[27];
        #pragma unroll
        for (int c=0;c<3;c++)
            #pragma unroll
            for (int di=0;di<3;di++)
                #pragma unroll
                for (int dj=0;dj<3;dj++)
                    v[c*9+di*3+dj] = xs[c*81 + (i+di)*9 + (j+dj)];
        int h = gi*7+i, w = gj*7+j;
        for (int f = 0; f < FC; f++) {
            float acc = bs[f];
            #pragma unroll
            for (int k=0;k<27;k++) acc += ks[f*27+k]*v[k];
            g_ymid[((b*FC+f)*HP + h)*WP + w] = acc;
        }
    }
}

// ---------------- K5: conv3 5x5 pad2, 32->64, relu. 8 oc per thread.
__global__ void k5_conv3(const float* __restrict__ w3, const float* __restrict__ b3) {
    __shared__ float ws[8*FC*25];   // 6400 floats = 25.6 KB
    __shared__ float bs[8];
    int z = blockIdx.z; int b = z >> 3; int og = z & 7;
    int tid = threadIdx.y*32 + threadIdx.x;
    for (int idx = tid; idx < 8*FC*25; idx += 256) ws[idx] = w3[og*8*FC*25 + idx];
    if (tid < 8) bs[tid] = b3[og*8 + tid];
    __syncthreads();
    int w = blockIdx.x*32 + threadIdx.x;
    int h = blockIdx.y*8 + threadIdx.y;
    if (h >= HP || w >= WP) return;
    float acc[8];
    #pragma unroll
    for (int o=0;o<8;o++) acc[o]=bs[o];
    for (int ic = 0; ic < FC; ic++) {
        const float* src = g_ymid + ((b*FC+ic)*HP)*WP;
        float tap[25];
        #pragma unroll
        for (int r=0;r<5;r++){
            int hh = h-2+r;
            #pragma unroll
            for (int s=0;s<5;s++){
                int ww = w-2+s;
                tap[r*5+s] = (hh>=0 && hh<HP && ww>=0 && ww<WP) ? src[hh*WP+ww] : 0.f;
            }
        }
        #pragma unroll
        for (int o=0;o<8;o++){
            const float* wp = ws + (o*FC+ic)*25;
            #pragma unroll
            for (int t=0;t<25;t++) acc[o] += tap[t]*wp[t];
        }
    }
    #pragma unroll
    for (int o=0;o<8;o++)
        g_y3[(((size_t)b*NF + og*8+o)*HP + h)*WP + w] = fmaxf(acc[o], 0.f);
}

// ---------------- K6: conv4 3x3 pad1 (64->12) + pixel-shuffle x2 + crop + mean add
__global__ void k6_conv4(const float* __restrict__ w4, const float* __restrict__ b4,
                         float* __restrict__ out) {
    __shared__ float ws[12*NF*9];  // 6912 floats = 27.6 KB
    __shared__ float bs[12];
    int b = blockIdx.z;
    int tid = threadIdx.y*32 + threadIdx.x;
    for (int idx = tid; idx < 12*NF*9; idx += 256) ws[idx] = w4[idx];
    if (tid < 12) bs[tid] = b4[tid];
    __syncthreads();
    int w = blockIdx.x*32 + threadIdx.x;   // < 640
    int h = blockIdx.y*8 + threadIdx.y;    // < 360
    float acc[12];
    #pragma unroll
    for (int o=0;o<12;o++) acc[o]=bs[o];
    for (int ic = 0; ic < NF; ic++) {
        const float* src = g_y3 + (((size_t)b*NF+ic)*HP)*WP;
        float tap[9];
        #pragma unroll
        for (int r=0;r<3;r++){
            int hh = h-1+r;   // max 360 < HP: real data, only top/left need zero
            #pragma unroll
            for (int s=0;s<3;s++){
                int ww = w-1+s;
                tap[r*3+s] = (hh>=0 && ww>=0) ? src[hh*WP+ww] : 0.f;
            }
        }
        #pragma unroll
        for (int o=0;o<12;o++){
            const float* wp = ws + (o*NF+ic)*9;
            #pragma unroll
            for (int t=0;t<9;t++) acc[o] += tap[t]*wp[t];
        }
    }
    #pragma unroll
    for (int o=0;o<12;o++){
        int co = o >> 2, s1 = (o >> 1) & 1, s2 = o & 1;
        out[((b*3+co)*720 + 2*h+s1)*1280 + 2*w+s2] = acc[o] + rgb_mean(co);
    }
}

// ---------------- launch ----------------
extern "C" void kernel_launch(void* const* d_in, const int* in_sizes, int n_in,
                              void* d_out, int out_size) {
    const float* x  = (const float*)d_in[0];
    const float* w1 = (const float*)d_in[1];
    const float* b1 = (const float*)d_in[2];
    const float* w2 = (const float*)d_in[3];
    const float* b2 = (const float*)d_in[4];
    const float* wk = (const float*)d_in[5];
    const float* bk = (const float*)d_in[6];
    const float* wb = (const float*)d_in[7];
    const float* bb = (const float*)d_in[8];
    const float* w3 = (const float*)d_in[9];
    const float* b3 = (const float*)d_in[10];
    const float* w4 = (const float*)d_in[11];
    const float* b4 = (const float*)d_in[12];
    float* out = (float*)d_out;

    k1_conv1<<<BP, 256>>>(x, w1, b1);
    k2_conv2<<<BP, 576>>>(w2, b2);
    k3_gemm<<<dim3((864+63)/64, (BP+127)/128), 256>>>(wk, bk, 864, 0);
    k3_gemm<<<dim3(1,           (BP+127)/128), 256>>>(wb, bb, 32, 1);
    k4_adapt<<<BP, 128>>>(x);
    k5_conv3<<<dim3((WP+31)/32, (HP+7)/8, B_*8), dim3(32,8)>>>(w3, b3);
    k6_conv4<<<dim3(W_/32, H_/8, B_), dim3(32,8)>>>(w4, b4, out);
}

// round 4
// speedup vs baseline: 2.2569x; 2.2569x over previous
#include <cuda_runtime.h>

#define B_ 4
#define C_ 3
#define H_ 360
#define W_ 640
#define HP 364
#define WP 644
#define GH 52
#define GW 92
#define BP (B_*GH*GW)   /* 19136 patches */
#define FH 64           /* F_HEAD */
#define FC 32           /* F_CH  */
#define NF 64           /* N_FEATS */

// ---------------- scratch (device globals; no allocation allowed) ----------
__device__ float g_feat1[BP*FH*25];        // conv1 out: [p][64][5x5]
__device__ float g_feat2[BP*FH*9];         // conv2 out: [p][64*9]
__device__ float g_kern [BP*FC*27];        // per-patch kernels [p][864]
__device__ float g_bias [BP*FC];           // per-patch bias [p][32]
__device__ float g_ymid [B_*FC*HP*WP];     // adaptive conv out
__device__ float g_y3  [(size_t)B_*NF*HP*WP]; // conv3 out

__device__ __forceinline__ float rgb_mean(int c) {
    return (c == 0) ? 0.4488f*255.0f : (c == 1) ? 0.4371f*255.0f : 0.404f*255.0f;
}

// ---------------- K1: patch extract (+mean sub, zero pad) + conv1 3x3 VALID + relu
__global__ void k1_conv1(const float* __restrict__ x, const float* __restrict__ w1,
                         const float* __restrict__ b1) {
    __shared__ float sp[C_*49];
    __shared__ float ws[FH*27];
    __shared__ float bs[FH];
    int p = blockIdx.x;
    int b = p / (GH*GW);
    int r = p % (GH*GW);
    int gi = r / GW, gj = r % GW;
    int tid = threadIdx.x;
    if (tid < C_*49) {
        int c = tid/49, q = tid%49;
        int i = q/7, j = q%7;
        int h = gi*7 + i, w = gj*7 + j;
        float v = 0.f;
        if (h < H_ && w < W_) v = x[((b*C_+c)*H_ + h)*W_ + w] - rgb_mean(c);
        sp[tid] = v;
    }
    for (int idx = tid; idx < FH*27; idx += blockDim.x) ws[idx] = w1[idx];
    if (tid < FH) bs[tid] = b1[tid];
    __syncthreads();
    for (int idx = tid; idx < FH*25; idx += blockDim.x) {
        int oc = idx / 25, q = idx % 25;
        int oy = q/5, ox = q%5;
        float acc = bs[oc];
        #pragma unroll
        for (int c = 0; c < 3; c++)
            #pragma unroll
            for (int ky = 0; ky < 3; ky++)
                #pragma unroll
                for (int kx = 0; kx < 3; kx++)
                    acc += sp[c*49 + (oy+ky)*7 + (ox+kx)] * ws[oc*27 + c*9 + ky*3 + kx];
        g_feat1[p*(FH*25) + idx] = fmaxf(acc, 0.f);
    }
}

// ---------------- K2: conv2 3x3 VALID (64->64) + relu.
// 4 patches/block, 256 threads = (patch, oc). Thread computes all 9 positions.
// Weights staged in smem in 16-ic chunks -> 81 FFMA per (25+9) LDS, no per-FMA LDG.
__global__ void k2_conv2(const float* __restrict__ w2, const float* __restrict__ b2) {
    __shared__ float sw[16*64*9];   // [icl][oc][t]   36.9 KB
    __shared__ float sf[4*16*25];   // [pl][icl][q]    6.4 KB
    int tid = threadIdx.x;          // 256
    int p0 = blockIdx.x*4;
    int pl = tid >> 6, oc = tid & 63;
    float bias = b2[oc];
    float acc[9];
    #pragma unroll
    for (int i = 0; i < 9; i++) acc[i] = 0.f;
    for (int c = 0; c < 4; c++) {
        int ic0 = c*16;
        __syncthreads();
        for (int idx = tid; idx < 16*64*9; idx += 256) {
            int icl = idx / 576; int rem = idx - icl*576;
            int o = rem / 9, t = rem - o*9;
            sw[idx] = w2[o*(FH*9) + (ic0+icl)*9 + t];
        }
        for (int idx = tid; idx < 4*400; idx += 256) {
            int pp = idx / 400; int rem = idx - pp*400;
            sf[idx] = g_feat1[(size_t)(p0+pp)*(FH*25) + ic0*25 + rem];
        }
        __syncthreads();
        for (int icl = 0; icl < 16; icl++) {
            float f[25];
            #pragma unroll
            for (int q = 0; q < 25; q++) f[q] = sf[pl*400 + icl*25 + q];
            const float* wp = sw + (icl*64 + oc)*9;
            #pragma unroll
            for (int ky = 0; ky < 3; ky++)
                #pragma unroll
                for (int kx = 0; kx < 3; kx++) {
                    float wv = wp[ky*3+kx];
                    #pragma unroll
                    for (int oy = 0; oy < 3; oy++)
                        #pragma unroll
                        for (int ox = 0; ox < 3; ox++)
                            acc[oy*3+ox] += f[(oy+ky)*5 + (ox+kx)] * wv;
                }
        }
    }
    float* dst = g_feat2 + (size_t)(p0+pl)*(FH*9) + oc*9;
    #pragma unroll
    for (int i = 0; i < 9; i++) dst[i] = fmaxf(acc[i] + bias, 0.f);
}

// ---------------- K3: fused GEMM  C[BP][896] = g_feat2[BP][576] * [wk;wb]^T + [bk;bb]
// cols 0..863 -> g_kern, cols 864..895 -> g_bias. 128x128x16 tiles, 8x8 micro,
// float4 smem reads: 4 LDS.128 per 64 FFMA.
__global__ void k3_gemm(const float* __restrict__ wk, const float* __restrict__ bk,
                        const float* __restrict__ wb, const float* __restrict__ bb) {
    const int K = FH*9;  // 576
    __shared__ __align__(16) float As[16][132];
    __shared__ __align__(16) float Bs[16][132];
    int tid = threadIdx.x;
    int m0 = blockIdx.y*128, n0 = blockIdx.x*128;
    int ty = tid >> 4, tx = tid & 15;
    float acc[8][8];
    #pragma unroll
    for (int i = 0; i < 8; i++)
        #pragma unroll
        for (int j = 0; j < 8; j++) acc[i][j] = 0.f;
    for (int k0 = 0; k0 < K; k0 += 16) {
        #pragma unroll
        for (int i = 0; i < 8; i++) {
            int idx = tid + i*256;
            int kk = idx & 15, mm = idx >> 4;
            int m = m0 + mm;
            As[kk][mm] = (m < BP) ? g_feat2[(size_t)m*K + k0 + kk] : 0.f;
        }
        #pragma unroll
        for (int i = 0; i < 8; i++) {
            int idx = tid + i*256;
            int kk = idx & 15, nn = idx >> 4;
            int n = n0 + nn;
            Bs[kk][nn] = (n < 864) ? wk[n*K + k0 + kk] : wb[(n-864)*K + k0 + kk];
        }
        __syncthreads();
        #pragma unroll
        for (int kk = 0; kk < 16; kk++) {
            float4 a0 = *(const float4*)&As[kk][ty*8];
            float4 a1 = *(const float4*)&As[kk][ty*8+4];
            float4 b0 = *(const float4*)&Bs[kk][tx*8];
            float4 b1 = *(const float4*)&Bs[kk][tx*8+4];
            float av[8] = {a0.x,a0.y,a0.z,a0.w,a1.x,a1.y,a1.z,a1.w};
            float bv[8] = {b0.x,b0.y,b0.z,b0.w,b1.x,b1.y,b1.z,b1.w};
            #pragma unroll
            for (int i = 0; i < 8; i++)
                #pragma unroll
                for (int j = 0; j < 8; j++)
                    acc[i][j] += av[i]*bv[j];
        }
        __syncthreads();
    }
    #pragma unroll
    for (int i = 0; i < 8; i++) {
        int m = m0 + ty*8 + i;
        if (m >= BP) continue;
        #pragma unroll
        for (int j = 0; j < 8; j++) {
            int n = n0 + tx*8 + j;
            float v = acc[i][j];
            if (n < 864) g_kern[(size_t)m*864 + n] = v + bk[n];
            else         g_bias[(size_t)m*32 + (n-864)] = v + bb[n-864];
        }
    }
}

// ---------------- K4: adaptive per-patch 3x3 conv (27 taps, per-patch zero pad)
__global__ void k4_adapt(const float* __restrict__ x) {
    __shared__ float ks[FC*27];
    __shared__ float bs[FC];
    __shared__ float xs[C_*81];   // 3 x 9 x 9, zero-padded patch
    int p = blockIdx.x;
    int b = p/(GH*GW); int r = p%(GH*GW);
    int gi = r/GW, gj = r%GW;
    int tid = threadIdx.x;  // 128
    for (int idx = tid; idx < FC*27; idx += blockDim.x) ks[idx] = g_kern[(size_t)p*(FC*27)+idx];
    if (tid < FC) bs[tid] = g_bias[(size_t)p*FC+tid];
    for (int idx = tid; idx < C_*81; idx += blockDim.x) xs[idx] = 0.f;
    __syncthreads();
    for (int idx = tid; idx < C_*49; idx += blockDim.x) {
        int c = idx/49, q = idx%49, i = q/7, j = q%7;
        int h = gi*7+i, w = gj*7+j;
        float v = 0.f;
        if (h < H_ && w < W_) v = x[((b*C_+c)*H_+h)*W_+w] - rgb_mean(c);
        xs[c*81 + (i+1)*9 + (j+1)] = v;
    }
    __syncthreads();
    if (tid < 49) {
        int i = tid/7, j = tid%7;
        float v[27];
        #pragma unroll
        for (int c = 0; c < 3; c++)
            #pragma unroll
            for (int di = 0; di < 3; di++)
                #pragma unroll
                for (int dj = 0; dj < 3; dj++)
                    v[c*9+di*3+dj] = xs[c*81 + (i+di)*9 + (j+dj)];
        int h = gi*7+i, w = gj*7+j;
        for (int f = 0; f < FC; f++) {
            float acc = bs[f];
            #pragma unroll
            for (int k = 0; k < 27; k++) acc += ks[f*27+k]*v[k];
            g_ymid[((b*FC+f)*HP + h)*WP + w] = acc;
        }
    }
}

// ---------------- K5: conv3 5x5 pad2, 32->64, relu.
// 64 threads (8,8). Thread = 8 px (w) x 8 oc = 64 acc. Smem input tile 64x8+halo.
// Per ic: 60 tap-LDS + 200 weight-LDS + 1600 FFMA  (1.17x issue ratio).
__global__ void __launch_bounds__(64) k5_conv3(const float* __restrict__ w3,
                                               const float* __restrict__ b3) {
    __shared__ float ws[8*FC*25];   // [o][ic][25]  25.6 KB
    __shared__ float bs[8];
    __shared__ float tile[12][68];
    int z = blockIdx.z; int b = z >> 3; int og = z & 7;
    int tx = threadIdx.x;   // 0..7
    int ty = threadIdx.y;   // 0..7
    int tid = ty*8 + tx;
    for (int idx = tid; idx < 8*FC*25; idx += 64) ws[idx] = w3[og*(8*FC*25) + idx];
    if (tid < 8) bs[tid] = b3[og*8 + tid];
    int h  = blockIdx.y*8 + ty;
    int w0 = blockIdx.x*64 + tx*8;
    int gh0 = blockIdx.y*8 - 2;
    int gw0 = blockIdx.x*64 - 2;
    float acc[8][8];
    #pragma unroll
    for (int o = 0; o < 8; o++)
        #pragma unroll
        for (int j = 0; j < 8; j++) acc[o][j] = 0.f;
    for (int ic = 0; ic < FC; ic++) {
        __syncthreads();   // WAR on tile (also covers ws on first iter)
        const float* src = g_ymid + ((b*FC+ic)*HP)*WP;
        for (int i = tid; i < 12*68; i += 64) {
            int r = i / 68, c2 = i - r*68;
            int hh = gh0 + r, ww = gw0 + c2;
            tile[r][c2] = (hh >= 0 && hh < HP && ww >= 0 && ww < WP) ? src[hh*WP+ww] : 0.f;
        }
        __syncthreads();
        #pragma unroll
        for (int r = 0; r < 5; r++) {
            float t[12];
            #pragma unroll
            for (int c2 = 0; c2 < 12; c2++) t[c2] = tile[ty + r][tx*8 + c2];
            #pragma unroll
            for (int o = 0; o < 8; o++) {
                const float* wrow = ws + (o*FC + ic)*25 + r*5;
                #pragma unroll
                for (int s = 0; s < 5; s++) {
                    float wv = wrow[s];
                    #pragma unroll
                    for (int j = 0; j < 8; j++)
                        acc[o][j] += t[j+s] * wv;
                }
            }
        }
    }
    if (h < HP) {
        #pragma unroll
        for (int o = 0; o < 8; o++) {
            float* dst = g_y3 + (((size_t)b*NF + og*8 + o)*HP + h)*WP;
            float bv = bs[o];
            #pragma unroll
            for (int j = 0; j < 8; j++) {
                int w = w0 + j;
                if (w < WP) dst[w] = fmaxf(acc[o][j] + bv, 0.f);
            }
        }
    }
}

// ---------------- K6: conv4 3x3 pad1 (64->12) + pixel-shuffle x2 + crop + mean add
// 128 threads (16,8). Thread = 4 px x 12 oc = 48 acc. Smem tile 64x8+halo.
__global__ void k6_conv4(const float* __restrict__ w4, const float* __restrict__ b4,
                         float* __restrict__ out) {
    __shared__ float ws[NF*12*9];   // [ic][o][t]  27.6 KB
    __shared__ float bs[12];
    __shared__ float tile[10][66];
    int b = blockIdx.z;
    int tx = threadIdx.x, ty = threadIdx.y;   // (16,8)
    int tid = ty*16 + tx;
    for (int idx = tid; idx < NF*12*9; idx += 128) {
        int ic = idx / 108; int rem = idx - ic*108;
        int o = rem / 9, t = rem - o*9;
        ws[idx] = w4[o*(NF*9) + ic*9 + t];
    }
    if (tid < 12) bs[tid] = b4[tid];
    int h  = blockIdx.y*8 + ty;
    int w0 = blockIdx.x*64 + tx*4;
    int gh0 = blockIdx.y*8 - 1;
    int gw0 = blockIdx.x*64 - 1;
    float acc[12][4];
    #pragma unroll
    for (int o = 0; o < 12; o++)
        #pragma unroll
        for (int j = 0; j < 4; j++) acc[o][j] = 0.f;
    for (int ic = 0; ic < NF; ic++) {
        __syncthreads();
        const float* src = g_y3 + (((size_t)b*NF + ic)*HP)*WP;
        for (int i = tid; i < 10*66; i += 128) {
            int r = i / 66, c2 = i - r*66;
            int hh = gh0 + r, ww = gw0 + c2;
            tile[r][c2] = (hh >= 0 && ww >= 0) ? src[hh*WP+ww] : 0.f;
        }
        __syncthreads();
        #pragma unroll
        for (int r = 0; r < 3; r++) {
            float t6[6];
            #pragma unroll
            for (int c2 = 0; c2 < 6; c2++) t6[c2] = tile[ty + r][tx*4 + c2];
            #pragma unroll
            for (int o = 0; o < 12; o++) {
                #pragma unroll
                for (int s = 0; s < 3; s++) {
                    float wv = ws[ic*108 + o*9 + r*3 + s];
                    #pragma unroll
                    for (int j = 0; j < 4; j++)
                        acc[o][j] += t6[j+s] * wv;
                }
            }
        }
    }
    #pragma unroll
    for (int o = 0; o < 12; o++) {
        int co = o >> 2, s1 = (o >> 1) & 1, s2 = o & 1;
        float mv = rgb_mean(co);
        float* dst = out + ((b*3+co)*720 + 2*h + s1)*1280;
        float bv = bs[o];
        #pragma unroll
        for (int j = 0; j < 4; j++)
            dst[2*(w0+j) + s2] = acc[o][j] + bv + mv;
    }
}

// ---------------- launch ----------------
extern "C" void kernel_launch(void* const* d_in, const int* in_sizes, int n_in,
                              void* d_out, int out_size) {
    const float* x  = (const float*)d_in[0];
    const float* w1 = (const float*)d_in[1];
    const float* b1 = (const float*)d_in[2];
    const float* w2 = (const float*)d_in[3];
    const float* b2 = (const float*)d_in[4];
    const float* wk = (const float*)d_in[5];
    const float* bk = (const float*)d_in[6];
    const float* wb = (const float*)d_in[7];
    const float* bb = (const float*)d_in[8];
    const float* w3 = (const float*)d_in[9];
    const float* b3 = (const float*)d_in[10];
    const float* w4 = (const float*)d_in[11];
    const float* b4 = (const float*)d_in[12];
    float* out = (float*)d_out;

    k1_conv1<<<BP, 256>>>(x, w1, b1);
    k2_conv2<<<BP/4, 256>>>(w2, b2);
    k3_gemm<<<dim3(7, (BP+127)/128), 256>>>(wk, bk, wb, bb);
    k4_adapt<<<BP, 128>>>(x);
    k5_conv3<<<dim3((WP+63)/64, (HP+7)/8, B_*8), dim3(8,8)>>>(w3, b3);
    k6_conv4<<<dim3(W_/64, H_/8, B_), dim3(16,8)>>>(w4, b4, out);
}

// round 5
// speedup vs baseline: 3.8964x; 1.7264x over previous
#include <cuda_runtime.h>
#include <cstdint>

#define B_ 4
#define C_ 3
#define H_ 360
#define W_ 640
#define HP 364
#define WP 644
#define GH 52
#define GW 92
#define BP (B_*GH*GW)   /* 19136 patches */
#define FH 64           /* F_HEAD */
#define FC 32           /* F_CH  */
#define NF 64           /* N_FEATS */

// ---------------- scratch (device globals; no allocation allowed) ----------
__device__ float g_feat1[BP*FH*25];        // conv1 out: [p][64][5x5]
__device__ float g_feat2[BP*FH*9];         // conv2 out: [p][64*9]
__device__ float g_kern [BP*FC*27];        // per-patch kernels [p][864]
__device__ float g_bias [BP*FC];           // per-patch bias [p][32]
__device__ float g_ymid [B_*FC*HP*WP];     // adaptive conv out
__device__ float g_y3  [(size_t)B_*NF*HP*WP]; // conv3 out
__device__ float g_wt  [25*FC*NF];         // conv3 weights transposed [tap][ic][oc]

__device__ __forceinline__ float rgb_mean(int c) {
    return (c == 0) ? 0.4488f*255.0f : (c == 1) ? 0.4371f*255.0f : 0.404f*255.0f;
}

__device__ __forceinline__ uint32_t tf32_bits(float f) {
    uint32_t u;
    asm("cvt.rna.tf32.f32 %0, %1;" : "=r"(u) : "f"(f));
    return u;
}

// ---------------- K1: patch extract (+mean sub, zero pad) + conv1 3x3 VALID + relu
__global__ void k1_conv1(const float* __restrict__ x, const float* __restrict__ w1,
                         const float* __restrict__ b1) {
    __shared__ float sp[C_*49];
    __shared__ float ws[FH*27];
    __shared__ float bs[FH];
    int p = blockIdx.x;
    int b = p / (GH*GW);
    int r = p % (GH*GW);
    int gi = r / GW, gj = r % GW;
    int tid = threadIdx.x;
    if (tid < C_*49) {
        int c = tid/49, q = tid%49;
        int i = q/7, j = q%7;
        int h = gi*7 + i, w = gj*7 + j;
        float v = 0.f;
        if (h < H_ && w < W_) v = x[((b*C_+c)*H_ + h)*W_ + w] - rgb_mean(c);
        sp[tid] = v;
    }
    for (int idx = tid; idx < FH*27; idx += blockDim.x) ws[idx] = w1[idx];
    if (tid < FH) bs[tid] = b1[tid];
    __syncthreads();
    for (int idx = tid; idx < FH*25; idx += blockDim.x) {
        int oc = idx / 25, q = idx % 25;
        int oy = q/5, ox = q%5;
        float acc = bs[oc];
        #pragma unroll
        for (int c = 0; c < 3; c++)
            #pragma unroll
            for (int ky = 0; ky < 3; ky++)
                #pragma unroll
                for (int kx = 0; kx < 3; kx++)
                    acc += sp[c*49 + (oy+ky)*7 + (ox+kx)] * ws[oc*27 + c*9 + ky*3 + kx];
        g_feat1[p*(FH*25) + idx] = fmaxf(acc, 0.f);
    }
}

// ---------------- K2: conv2 3x3 VALID (64->64) + relu.
__global__ void k2_conv2(const float* __restrict__ w2, const float* __restrict__ b2) {
    __shared__ float sw[16*64*9];   // [icl][oc][t]   36.9 KB
    __shared__ float sf[4*16*25];   // [pl][icl][q]    6.4 KB
    int tid = threadIdx.x;          // 256
    int p0 = blockIdx.x*4;
    int pl = tid >> 6, oc = tid & 63;
    float bias = b2[oc];
    float acc[9];
    #pragma unroll
    for (int i = 0; i < 9; i++) acc[i] = 0.f;
    for (int c = 0; c < 4; c++) {
        int ic0 = c*16;
        __syncthreads();
        for (int idx = tid; idx < 16*64*9; idx += 256) {
            int icl = idx / 576; int rem = idx - icl*576;
            int o = rem / 9, t = rem - o*9;
            sw[idx] = w2[o*(FH*9) + (ic0+icl)*9 + t];
        }
        for (int idx = tid; idx < 4*400; idx += 256) {
            int pp = idx / 400; int rem = idx - pp*400;
            sf[idx] = g_feat1[(size_t)(p0+pp)*(FH*25) + ic0*25 + rem];
        }
        __syncthreads();
        for (int icl = 0; icl < 16; icl++) {
            float f[25];
            #pragma unroll
            for (int q = 0; q < 25; q++) f[q] = sf[pl*400 + icl*25 + q];
            const float* wp = sw + (icl*64 + oc)*9;
            #pragma unroll
            for (int ky = 0; ky < 3; ky++)
                #pragma unroll
                for (int kx = 0; kx < 3; kx++) {
                    float wv = wp[ky*3+kx];
                    #pragma unroll
                    for (int oy = 0; oy < 3; oy++)
                        #pragma unroll
                        for (int ox = 0; ox < 3; ox++)
                            acc[oy*3+ox] += f[(oy+ky)*5 + (ox+kx)] * wv;
                }
        }
    }
    float* dst = g_feat2 + (size_t)(p0+pl)*(FH*9) + oc*9;
    #pragma unroll
    for (int i = 0; i < 9; i++) dst[i] = fmaxf(acc[i] + bias, 0.f);
}

// ---------------- K3: fused GEMM  C[BP][896] = g_feat2[BP][576] * [wk;wb]^T + [bk;bb]
__global__ void k3_gemm(const float* __restrict__ wk, const float* __restrict__ bk,
                        const float* __restrict__ wb, const float* __restrict__ bb) {
    const int K = FH*9;  // 576
    __shared__ __align__(16) float As[16][132];
    __shared__ __align__(16) float Bs[16][132];
    int tid = threadIdx.x;
    int m0 = blockIdx.y*128, n0 = blockIdx.x*128;
    int ty = tid >> 4, tx = tid & 15;
    float acc[8][8];
    #pragma unroll
    for (int i = 0; i < 8; i++)
        #pragma unroll
        for (int j = 0; j < 8; j++) acc[i][j] = 0.f;
    for (int k0 = 0; k0 < K; k0 += 16) {
        #pragma unroll
        for (int i = 0; i < 8; i++) {
            int idx = tid + i*256;
            int kk = idx & 15, mm = idx >> 4;
            int m = m0 + mm;
            As[kk][mm] = (m < BP) ? g_feat2[(size_t)m*K + k0 + kk] : 0.f;
        }
        #pragma unroll
        for (int i = 0; i < 8; i++) {
            int idx = tid + i*256;
            int kk = idx & 15, nn = idx >> 4;
            int n = n0 + nn;
            Bs[kk][nn] = (n < 864) ? wk[n*K + k0 + kk] : wb[(n-864)*K + k0 + kk];
        }
        __syncthreads();
        #pragma unroll
        for (int kk = 0; kk < 16; kk++) {
            float4 a0 = *(const float4*)&As[kk][ty*8];
            float4 a1 = *(const float4*)&As[kk][ty*8+4];
            float4 b0 = *(const float4*)&Bs[kk][tx*8];
            float4 b1 = *(const float4*)&Bs[kk][tx*8+4];
            float av[8] = {a0.x,a0.y,a0.z,a0.w,a1.x,a1.y,a1.z,a1.w};
            float bv[8] = {b0.x,b0.y,b0.z,b0.w,b1.x,b1.y,b1.z,b1.w};
            #pragma unroll
            for (int i = 0; i < 8; i++)
                #pragma unroll
                for (int j = 0; j < 8; j++)
                    acc[i][j] += av[i]*bv[j];
        }
        __syncthreads();
    }
    #pragma unroll
    for (int i = 0; i < 8; i++) {
        int m = m0 + ty*8 + i;
        if (m >= BP) continue;
        #pragma unroll
        for (int j = 0; j < 8; j++) {
            int n = n0 + tx*8 + j;
            float v = acc[i][j];
            if (n < 864) g_kern[(size_t)m*864 + n] = v + bk[n];
            else         g_bias[(size_t)m*32 + (n-864)] = v + bb[n-864];
        }
    }
}

// ---------------- K4: adaptive per-patch 3x3 conv
__global__ void k4_adapt(const float* __restrict__ x) {
    __shared__ float ks[FC*27];
    __shared__ float bs[FC];
    __shared__ float xs[C_*81];   // 3 x 9 x 9, zero-padded patch
    int p = blockIdx.x;
    int b = p/(GH*GW); int r = p%(GH*GW);
    int gi = r/GW, gj = r%GW;
    int tid = threadIdx.x;  // 128
    for (int idx = tid; idx < FC*27; idx += blockDim.x) ks[idx] = g_kern[(size_t)p*(FC*27)+idx];
    if (tid < FC) bs[tid] = g_bias[(size_t)p*FC+tid];
    for (int idx = tid; idx < C_*81; idx += blockDim.x) xs[idx] = 0.f;
    __syncthreads();
    for (int idx = tid; idx < C_*49; idx += blockDim.x) {
        int c = idx/49, q = idx%49, i = q/7, j = q%7;
        int h = gi*7+i, w = gj*7+j;
        float v = 0.f;
        if (h < H_ && w < W_) v = x[((b*C_+c)*H_+h)*W_+w] - rgb_mean(c);
        xs[c*81 + (i+1)*9 + (j+1)] = v;
    }
    __syncthreads();
    if (tid < 49) {
        int i = tid/7, j = tid%7;
        float v[27];
        #pragma unroll
        for (int c = 0; c < 3; c++)
            #pragma unroll
            for (int di = 0; di < 3; di++)
                #pragma unroll
                for (int dj = 0; dj < 3; dj++)
                    v[c*9+di*3+dj] = xs[c*81 + (i+di)*9 + (j+dj)];
        int h = gi*7+i, w = gj*7+j;
        for (int f = 0; f < FC; f++) {
            float acc = bs[f];
            #pragma unroll
            for (int k = 0; k < 27; k++) acc += ks[f*27+k]*v[k];
            g_ymid[((b*FC+f)*HP + h)*WP + w] = acc;
        }
    }
}

// ---------------- K5w: transpose conv3 weights w3[oc][ic][25] -> g_wt[tap][ic][oc]
__global__ void k5w_transpose(const float* __restrict__ w3) {
    int i = blockIdx.x*256 + threadIdx.x;
    if (i >= 25*FC*NF) return;
    int tap = i / (FC*NF);
    int rem = i - tap*(FC*NF);
    int ic = rem >> 6, oc = rem & 63;
    g_wt[i] = w3[(oc*FC + ic)*25 + tap];
}

// ---------------- K5: conv3 5x5 pad2, 32->64, relu — tf32 mma.sync implicit GEMM.
// Block 128 thr (4 warps). Tile: 64 oc x 128 pixels (8 rows x 16 cols).
// M = oc (warp w -> oc 16w..16w+15, one m16 tile), N = pixels (16 n8-tiles),
// K = 800 = 25 taps x 32 ic (4 k8-steps per tap).
// Input tile [12][20][ic pad 36] and per-tap weight slab [32][oc pad 72] staged
// in smem pre-converted to tf32 bits; both fragment loads are bank-conflict-free
// ((4g+t) and (8t+g) patterns).
__global__ void __launch_bounds__(128) k5_conv3(const float* __restrict__ b3) {
    __shared__ uint32_t tileS[12*20*36];   // 34560 B
    __shared__ uint32_t wslab[32*72];      //  9216 B
    __shared__ float sbias[NF];
    int b  = blockIdx.z;
    int by = blockIdx.y, bx = blockIdx.x;
    int tid = threadIdx.x;
    int warp = tid >> 5, lane = tid & 31;
    int g = lane >> 2, t = lane & 3;
    int gh0 = by*8 - 2, gw0 = bx*16 - 2;

    // stage input tile (32 ic x 12x20 window), tf32-converted
    for (int i = tid; i < FC*240; i += 128) {
        int ic = i / 240, pos = i - ic*240;
        int r = pos / 20, c = pos - r*20;
        int hh = gh0 + r, ww = gw0 + c;
        float v = 0.f;
        if (hh >= 0 && hh < HP && ww >= 0 && ww < WP)
            v = g_ymid[((b*FC + ic)*HP + hh)*WP + ww];
        tileS[(r*20 + c)*36 + ic] = tf32_bits(v);
    }
    if (tid < NF) sbias[tid] = b3[tid];

    float acc[16][4];
    #pragma unroll
    for (int j = 0; j < 16; j++)
        #pragma unroll
        for (int q = 0; q < 4; q++) acc[j][q] = 0.f;

    for (int tap = 0; tap < 25; tap++) {
        __syncthreads();   // WAR on wslab; first iter also covers tileS/sbias
        for (int i = tid; i < FC*NF; i += 128) {
            int ic = i >> 6, oc = i & 63;
            wslab[ic*72 + oc] = tf32_bits(g_wt[tap*(FC*NF) + i]);
        }
        __syncthreads();
        int dtr = tap / 5, dtc = tap - dtr*5;
        #pragma unroll
        for (int ks = 0; ks < 4; ks++) {
            int ic0 = ks*8;
            uint32_t a0 = wslab[(ic0+t)*72   + 16*warp + g];
            uint32_t a1 = wslab[(ic0+t)*72   + 16*warp + g + 8];
            uint32_t a2 = wslab[(ic0+t+4)*72 + 16*warp + g];
            uint32_t a3 = wslab[(ic0+t+4)*72 + 16*warp + g + 8];
            #pragma unroll
            for (int j = 0; j < 16; j++) {
                int jr = j >> 1, jc = (j & 1)*8;
                const uint32_t* bp = &tileS[((jr+dtr)*20 + jc + g + dtc)*36 + ic0 + t];
                uint32_t b0 = bp[0], b1 = bp[4];
                asm volatile(
                    "mma.sync.aligned.m16n8k8.row.col.f32.tf32.tf32.f32 "
                    "{%0,%1,%2,%3}, {%4,%5,%6,%7}, {%8,%9}, {%0,%1,%2,%3};\n"
                    : "+f"(acc[j][0]), "+f"(acc[j][1]), "+f"(acc[j][2]), "+f"(acc[j][3])
                    : "r"(a0), "r"(a1), "r"(a2), "r"(a3), "r"(b0), "r"(b1));
            }
        }
    }

    // epilogue: D rows = oc (16w+g, +8), cols = pixel (2t, 2t+1) within each n-tile
    int oc0 = 16*warp + g;
    float bv0 = sbias[oc0], bv1 = sbias[oc0 + 8];
    #pragma unroll
    for (int j = 0; j < 16; j++) {
        int jr = j >> 1, jc = (j & 1)*8;
        int py = by*8 + jr;
        if (py >= HP) continue;
        int px = bx*16 + jc + 2*t;
        float* base0 = g_y3 + (((size_t)b*NF + oc0)*HP + py)*WP;
        float* base1 = g_y3 + (((size_t)b*NF + oc0 + 8)*HP + py)*WP;
        if (px < WP) {
            base0[px] = fmaxf(acc[j][0] + bv0, 0.f);
            base1[px] = fmaxf(acc[j][2] + bv1, 0.f);
        }
        if (px + 1 < WP) {
            base0[px+1] = fmaxf(acc[j][1] + bv0, 0.f);
            base1[px+1] = fmaxf(acc[j][3] + bv1, 0.f);
        }
    }
}

// ---------------- K6: conv4 3x3 pad1 (64->12) + pixel-shuffle x2 + crop + mean add
__global__ void k6_conv4(const float* __restrict__ w4, const float* __restrict__ b4,
                         float* __restrict__ out) {
    __shared__ float ws[NF*12*9];   // [ic][o][t]  27.6 KB
    __shared__ float bs[12];
    __shared__ float tile[10][66];
    int b = blockIdx.z;
    int tx = threadIdx.x, ty = threadIdx.y;   // (16,8)
    int tid = ty*16 + tx;
    for (int idx = tid; idx < NF*12*9; idx += 128) {
        int ic = idx / 108; int rem = idx - ic*108;
        int o = rem / 9, t = rem - o*9;
        ws[idx] = w4[o*(NF*9) + ic*9 + t];
    }
    if (tid < 12) bs[tid] = b4[tid];
    int h  = blockIdx.y*8 + ty;
    int w0 = blockIdx.x*64 + tx*4;
    int gh0 = blockIdx.y*8 - 1;
    int gw0 = blockIdx.x*64 - 1;
    float acc[12][4];
    #pragma unroll
    for (int o = 0; o < 12; o++)
        #pragma unroll
        for (int j = 0; j < 4; j++) acc[o][j] = 0.f;
    for (int ic = 0; ic < NF; ic++) {
        __syncthreads();
        const float* src = g_y3 + (((size_t)b*NF + ic)*HP)*WP;
        for (int i = tid; i < 10*66; i += 128) {
            int r = i / 66, c2 = i - r*66;
            int hh = gh0 + r, ww = gw0 + c2;
            tile[r][c2] = (hh >= 0 && ww >= 0) ? src[hh*WP+ww] : 0.f;
        }
        __syncthreads();
        #pragma unroll
        for (int r = 0; r < 3; r++) {
            float t6[6];
            #pragma unroll
            for (int c2 = 0; c2 < 6; c2++) t6[c2] = tile[ty + r][tx*4 + c2];
            #pragma unroll
            for (int o = 0; o < 12; o++) {
                #pragma unroll
                for (int s = 0; s < 3; s++) {
                    float wv = ws[ic*108 + o*9 + r*3 + s];
                    #pragma unroll
                    for (int j = 0; j < 4; j++)
                        acc[o][j] += t6[j+s] * wv;
                }
            }
        }
    }
    #pragma unroll
    for (int o = 0; o < 12; o++) {
        int co = o >> 2, s1 = (o >> 1) & 1, s2 = o & 1;
        float mv = rgb_mean(co);
        float* dst = out + ((b*3+co)*720 + 2*h + s1)*1280;
        float bv = bs[o];
        #pragma unroll
        for (int j = 0; j < 4; j++)
            dst[2*(w0+j) + s2] = acc[o][j] + bv + mv;
    }
}

// ---------------- launch ----------------
extern "C" void kernel_launch(void* const* d_in, const int* in_sizes, int n_in,
                              void* d_out, int out_size) {
    const float* x  = (const float*)d_in[0];
    const float* w1 = (const float*)d_in[1];
    const float* b1 = (const float*)d_in[2];
    const float* w2 = (const float*)d_in[3];
    const float* b2 = (const float*)d_in[4];
    const float* wk = (const float*)d_in[5];
    const float* bk = (const float*)d_in[6];
    const float* wb = (const float*)d_in[7];
    const float* bb = (const float*)d_in[8];
    const float* w3 = (const float*)d_in[9];
    const float* b3 = (const float*)d_in[10];
    const float* w4 = (const float*)d_in[11];
    const float* b4 = (const float*)d_in[12];
    float* out = (float*)d_out;

    k5w_transpose<<<(25*FC*NF + 255)/256, 256>>>(w3);
    k1_conv1<<<BP, 256>>>(x, w1, b1);
    k2_conv2<<<BP/4, 256>>>(w2, b2);
    k3_gemm<<<dim3(7, (BP+127)/128), 256>>>(wk, bk, wb, bb);
    k4_adapt<<<BP, 128>>>(x);
    k5_conv3<<<dim3((WP+15)/16, (HP+7)/8, B_), 128>>>(b3);
    k6_conv4<<<dim3(W_/64, H_/8, B_), dim3(16,8)>>>(w4, b4, out);
}

// round 6
// speedup vs baseline: 5.3217x; 1.3658x over previous
#include <cuda_runtime.h>
#include <cstdint>

#define B_ 4
#define C_ 3
#define H_ 360
#define W_ 640
#define HP 364
#define WP 644
#define GH 52
#define GW 92
#define BP (B_*GH*GW)   /* 19136 patches */
#define FH 64           /* F_HEAD */
#define FC 32           /* F_CH  */
#define NF 64           /* N_FEATS */

// ---------------- scratch (device globals; no allocation allowed) ----------
__device__ __align__(16) float g_feat1[BP*FH*25];   // conv1 out: [p][pos25][ic64]
__device__ __align__(16) float g_feat2[BP*FH*9];    // conv2 out: [p][oc*9+pos]
__device__ __align__(16) float g_kern [BP*FC*27];   // per-patch kernels [p][864]
__device__ __align__(16) float g_bias [BP*FC];      // per-patch bias [p][32]
__device__ __align__(16) float g_ymid [B_*FC*HP*WP];     // adaptive conv out
__device__ __align__(16) float g_y3  [(size_t)B_*NF*HP*WP]; // conv3 out
__device__ __align__(16) float g_wt  [25*FC*NF];    // conv3 w transposed [tap][ic][oc]
__device__ __align__(16) float g_wt2 [9*FH*FH];     // conv2 w transposed [tap][ic][oc]

__device__ __forceinline__ float rgb_mean(int c) {
    return (c == 0) ? 0.4488f*255.0f : (c == 1) ? 0.4371f*255.0f : 0.404f*255.0f;
}

__device__ __forceinline__ uint32_t tf32_bits(float f) {
    uint32_t u;
    asm("cvt.rna.tf32.f32 %0, %1;" : "=r"(u) : "f"(f));
    return u;
}

#define MMA_TF32(ACC, A0,A1,A2,A3, B0,B1) \
    asm volatile("mma.sync.aligned.m16n8k8.row.col.f32.tf32.tf32.f32 " \
        "{%0,%1,%2,%3}, {%4,%5,%6,%7}, {%8,%9}, {%0,%1,%2,%3};\n" \
        : "+f"((ACC)[0]), "+f"((ACC)[1]), "+f"((ACC)[2]), "+f"((ACC)[3]) \
        : "r"(A0), "r"(A1), "r"(A2), "r"(A3), "r"(B0), "r"(B1))

// ---------------- weight transposes ----------------
__global__ void k5w_transpose(const float* __restrict__ w3) {
    int i = blockIdx.x*256 + threadIdx.x;
    if (i >= 25*FC*NF) return;
    int tap = i / (FC*NF);
    int rem = i - tap*(FC*NF);
    int ic = rem >> 6, oc = rem & 63;
    g_wt[i] = w3[(oc*FC + ic)*25 + tap];
}
__global__ void k2w_transpose(const float* __restrict__ w2) {
    int i = blockIdx.x*256 + threadIdx.x;
    if (i >= 9*FH*FH) return;
    int tap = i / (FH*FH);
    int rem = i - tap*(FH*FH);
    int ic = rem >> 6, oc = rem & 63;
    g_wt2[i] = w2[(oc*FH + ic)*9 + tap];
}

// ---------------- K1: patch extract + conv1 3x3 VALID + relu
// Output layout changed to [p][pos(25)][ic(64)] for k2's mma staging.
__global__ void k1_conv1(const float* __restrict__ x, const float* __restrict__ w1,
                         const float* __restrict__ b1) {
    __shared__ float sp[C_*49];
    __shared__ float ws[FH*27];
    __shared__ float bs[FH];
    int p = blockIdx.x;
    int b = p / (GH*GW);
    int r = p % (GH*GW);
    int gi = r / GW, gj = r % GW;
    int tid = threadIdx.x;
    if (tid < C_*49) {
        int c = tid/49, q = tid%49;
        int i = q/7, j = q%7;
        int h = gi*7 + i, w = gj*7 + j;
        float v = 0.f;
        if (h < H_ && w < W_) v = x[((b*C_+c)*H_ + h)*W_ + w] - rgb_mean(c);
        sp[tid] = v;
    }
    for (int idx = tid; idx < FH*27; idx += blockDim.x) ws[idx] = w1[idx];
    if (tid < FH) bs[tid] = b1[tid];
    __syncthreads();
    for (int idx = tid; idx < FH*25; idx += blockDim.x) {
        int q = idx >> 6, oc = idx & 63;   // pos-major, ic contiguous
        int oy = q/5, ox = q%5;
        float acc = bs[oc];
        #pragma unroll
        for (int c = 0; c < 3; c++)
            #pragma unroll
            for (int ky = 0; ky < 3; ky++)
                #pragma unroll
                for (int kx = 0; kx < 3; kx++)
                    acc += sp[c*49 + (oy+ky)*7 + (ox+kx)] * ws[oc*27 + c*9 + ky*3 + kx];
        g_feat1[(size_t)p*(FH*25) + idx] = fmaxf(acc, 0.f);
    }
}

// ---------------- K2: conv2 3x3 VALID (64->64) + relu — tf32 mma implicit GEMM.
// Block 128 thr (4 warps). M=64 oc (warp->m16), N=36 (4 patches x 9 pos, 5 n8
// tiles incl. 4 pad cols), K=576 tap-major (9 taps x 8 k8-steps).
__global__ void __launch_bounds__(128) k2_conv2(const float* __restrict__ b2) {
    __shared__ uint32_t sf[4*25*68];    // [pl*25+pos][ic pad 68]  27.2 KB
    __shared__ uint32_t wslab[64*72];   // [ic][oc pad 72]         18.4 KB
    int tid = threadIdx.x;
    int p0 = blockIdx.x*4;
    int warp = tid >> 5, lane = tid & 31;
    int g = lane >> 2, t = lane & 3;

    // stage feat1 for 4 patches, tf32-converted (coalesced float4)
    for (int i = tid; i < 4*400; i += 128) {   // 400 float4 per patch
        int pl = i / 400, rem = i - pl*400;
        int pos = rem >> 4, c = rem & 15;
        float4 v = *(const float4*)&g_feat1[(size_t)(p0+pl)*1600 + pos*64 + 4*c];
        uint32_t* dst = &sf[(pl*25+pos)*68 + 4*c];
        dst[0]=tf32_bits(v.x); dst[1]=tf32_bits(v.y);
        dst[2]=tf32_bits(v.z); dst[3]=tf32_bits(v.w);
    }

    // per-lane column precompute (5 n-tiles; cols >=36 clamped, discarded later)
    int rB[5];
    #pragma unroll
    for (int j = 0; j < 5; j++) {
        int col = 8*j + g;
        int cc = (col < 36) ? col : 35;
        int pl = cc/9, pos = cc - pl*9;
        int oy = pos/3, ox = pos - oy*3;
        rB[j] = pl*25 + oy*5 + ox;
    }
    float acc[5][4];
    #pragma unroll
    for (int j = 0; j < 5; j++)
        #pragma unroll
        for (int q = 0; q < 4; q++) acc[j][q] = 0.f;

    for (int tap = 0; tap < 9; tap++) {
        __syncthreads();   // WAR on wslab (first iter also covers sf)
        for (int i = tid; i < 1024; i += 128) {   // 64x64 weights as float4
            int ic = i >> 4, c = i & 15;
            float4 v = *(const float4*)&g_wt2[tap*4096 + ic*64 + 4*c];
            uint32_t* dst = &wslab[ic*72 + 4*c];
            dst[0]=tf32_bits(v.x); dst[1]=tf32_bits(v.y);
            dst[2]=tf32_bits(v.z); dst[3]=tf32_bits(v.w);
        }
        __syncthreads();
        int dtr = tap/3, dtc = tap - dtr*3;
        int roff = (dtr*5 + dtc)*68;
        #pragma unroll
        for (int ks = 0; ks < 8; ks++) {
            int kl = ks*8;
            uint32_t a0 = wslab[(kl+t)*72   + 16*warp + g];
            uint32_t a1 = wslab[(kl+t)*72   + 16*warp + g + 8];
            uint32_t a2 = wslab[(kl+t+4)*72 + 16*warp + g];
            uint32_t a3 = wslab[(kl+t+4)*72 + 16*warp + g + 8];
            #pragma unroll
            for (int j = 0; j < 5; j++) {
                const uint32_t* bp = &sf[rB[j]*68 + roff + kl + t];
                uint32_t b0 = bp[0], b1 = bp[4];
                MMA_TF32(acc[j], a0,a1,a2,a3, b0,b1);
            }
        }
    }

    // epilogue: rows oc0/oc0+8, cols 2t,2t+1 per n-tile
    int oc0 = 16*warp + g;
    float bv0 = b2[oc0], bv1 = b2[oc0+8];
    #pragma unroll
    for (int j = 0; j < 5; j++) {
        #pragma unroll
        for (int h2 = 0; h2 < 2; h2++) {
            int col = 8*j + 2*t + h2;
            if (col >= 36) continue;
            int pl = col/9, pos = col - pl*9;
            float* d = g_feat2 + (size_t)(p0+pl)*576;
            d[oc0*9 + pos]     = fmaxf(acc[j][h2]   + bv0, 0.f);
            d[(oc0+8)*9 + pos] = fmaxf(acc[j][2+h2] + bv1, 0.f);
        }
    }
}

// ---------------- K3: fused GEMM C[BP][896] = feat2[BP][576] x [wk;wb]^T + [bk;bb]
// tf32 mma: block 128 thr (4 warps), tile M=128 x N=64, K-chunks of 32.
// smem [m][k pad 36]/[n][k pad 36]: fragment LDS bank-bijective (stride=4 mod 32).
__global__ void __launch_bounds__(128) k3_gemm(const float* __restrict__ wk,
                                               const float* __restrict__ bk,
                                               const float* __restrict__ wb,
                                               const float* __restrict__ bb) {
    __shared__ uint32_t As[128*36];   // 18.4 KB
    __shared__ uint32_t Bs[64*36];    //  9.2 KB
    int tid = threadIdx.x;
    int warp = tid >> 5, lane = tid & 31;
    int g = lane >> 2, t = lane & 3;
    int m0 = blockIdx.y*128, n0 = blockIdx.x*64;
    int c = tid & 7, r0 = tid >> 3;

    float acc[2][8][4];
    #pragma unroll
    for (int mt = 0; mt < 2; mt++)
        #pragma unroll
        for (int j = 0; j < 8; j++)
            #pragma unroll
            for (int q = 0; q < 4; q++) acc[mt][j][q] = 0.f;

    for (int k0 = 0; k0 < 576; k0 += 32) {
        __syncthreads();
        #pragma unroll
        for (int rr = r0; rr < 128; rr += 16) {
            int m = m0 + rr;
            float4 v = make_float4(0.f,0.f,0.f,0.f);
            if (m < BP) v = *(const float4*)&g_feat2[(size_t)m*576 + k0 + 4*c];
            uint32_t* dst = &As[rr*36 + 4*c];
            dst[0]=tf32_bits(v.x); dst[1]=tf32_bits(v.y);
            dst[2]=tf32_bits(v.z); dst[3]=tf32_bits(v.w);
        }
        #pragma unroll
        for (int rr = r0; rr < 64; rr += 16) {
            int n = n0 + rr;
            const float* src = (n < 864) ? &wk[(size_t)n*576] : &wb[(size_t)(n-864)*576];
            float4 v = *(const float4*)&src[k0 + 4*c];
            uint32_t* dst = &Bs[rr*36 + 4*c];
            dst[0]=tf32_bits(v.x); dst[1]=tf32_bits(v.y);
            dst[2]=tf32_bits(v.z); dst[3]=tf32_bits(v.w);
        }
        __syncthreads();
        #pragma unroll
        for (int ks = 0; ks < 4; ks++) {
            int kl = ks*8;
            uint32_t bf[8][2];
            #pragma unroll
            for (int j = 0; j < 8; j++) {
                bf[j][0] = Bs[(8*j+g)*36 + kl + t];
                bf[j][1] = Bs[(8*j+g)*36 + kl + t + 4];
            }
            #pragma unroll
            for (int mt = 0; mt < 2; mt++) {
                int mb = 32*warp + 16*mt;
                uint32_t a0 = As[(mb+g)*36   + kl + t];
                uint32_t a1 = As[(mb+g+8)*36 + kl + t];
                uint32_t a2 = As[(mb+g)*36   + kl + t + 4];
                uint32_t a3 = As[(mb+g+8)*36 + kl + t + 4];
                #pragma unroll
                for (int j = 0; j < 8; j++)
                    MMA_TF32(acc[mt][j], a0,a1,a2,a3, bf[j][0], bf[j][1]);
            }
        }
    }

    #pragma unroll
    for (int mt = 0; mt < 2; mt++) {
        int m = m0 + 32*warp + 16*mt + g;
        #pragma unroll
        for (int j = 0; j < 8; j++) {
            #pragma unroll
            for (int h2 = 0; h2 < 2; h2++) {
                int n = n0 + 8*j + 2*t + h2;
                float v0 = acc[mt][j][h2], v1 = acc[mt][j][2+h2];
                if (n < 864) {
                    float bv = bk[n];
                    if (m < BP)     g_kern[(size_t)m*864 + n]     = v0 + bv;
                    if (m+8 < BP)   g_kern[(size_t)(m+8)*864 + n] = v1 + bv;
                } else {
                    float bv = bb[n-864];
                    if (m < BP)     g_bias[(size_t)m*32 + (n-864)]     = v0 + bv;
                    if (m+8 < BP)   g_bias[(size_t)(m+8)*32 + (n-864)] = v1 + bv;
                }
            }
        }
    }
}

// ---------------- K4: adaptive per-patch 3x3 conv
__global__ void k4_adapt(const float* __restrict__ x) {
    __shared__ float ks[FC*27];
    __shared__ float bs[FC];
    __shared__ float xs[C_*81];
    int p = blockIdx.x;
    int b = p/(GH*GW); int r = p%(GH*GW);
    int gi = r/GW, gj = r%GW;
    int tid = threadIdx.x;  // 128
    for (int idx = tid; idx < FC*27; idx += blockDim.x) ks[idx] = g_kern[(size_t)p*(FC*27)+idx];
    if (tid < FC) bs[tid] = g_bias[(size_t)p*FC+tid];
    for (int idx = tid; idx < C_*81; idx += blockDim.x) xs[idx] = 0.f;
    __syncthreads();
    for (int idx = tid; idx < C_*49; idx += blockDim.x) {
        int c = idx/49, q = idx%49, i = q/7, j = q%7;
        int h = gi*7+i, w = gj*7+j;
        float v = 0.f;
        if (h < H_ && w < W_) v = x[((b*C_+c)*H_+h)*W_+w] - rgb_mean(c);
        xs[c*81 + (i+1)*9 + (j+1)] = v;
    }
    __syncthreads();
    if (tid < 49) {
        int i = tid/7, j = tid%7;
        float v[27];
        #pragma unroll
        for (int c = 0; c < 3; c++)
            #pragma unroll
            for (int di = 0; di < 3; di++)
                #pragma unroll
                for (int dj = 0; dj < 3; dj++)
                    v[c*9+di*3+dj] = xs[c*81 + (i+di)*9 + (j+dj)];
        int h = gi*7+i, w = gj*7+j;
        for (int f = 0; f < FC; f++) {
            float acc = bs[f];
            #pragma unroll
            for (int k = 0; k < 27; k++) acc += ks[f*27+k]*v[k];
            g_ymid[((b*FC+f)*HP + h)*WP + w] = acc;
        }
    }
}

// ---------------- K5: conv3 5x5 pad2, 32->64, relu — tf32 mma implicit GEMM.
__global__ void __launch_bounds__(128) k5_conv3(const float* __restrict__ b3) {
    __shared__ uint32_t tileS[12*20*36];   // 34560 B
    __shared__ uint32_t wslab[32*72];      //  9216 B
    __shared__ float sbias[NF];
    int b  = blockIdx.z;
    int by = blockIdx.y, bx = blockIdx.x;
    int tid = threadIdx.x;
    int warp = tid >> 5, lane = tid & 31;
    int g = lane >> 2, t = lane & 3;
    int gh0 = by*8 - 2, gw0 = bx*16 - 2;

    for (int i = tid; i < FC*240; i += 128) {
        int ic = i / 240, pos = i - ic*240;
        int r = pos / 20, c = pos - r*20;
        int hh = gh0 + r, ww = gw0 + c;
        float v = 0.f;
        if (hh >= 0 && hh < HP && ww >= 0 && ww < WP)
            v = g_ymid[((b*FC + ic)*HP + hh)*WP + ww];
        tileS[(r*20 + c)*36 + ic] = tf32_bits(v);
    }
    if (tid < NF) sbias[tid] = b3[tid];

    float acc[16][4];
    #pragma unroll
    for (int j = 0; j < 16; j++)
        #pragma unroll
        for (int q = 0; q < 4; q++) acc[j][q] = 0.f;

    for (int tap = 0; tap < 25; tap++) {
        __syncthreads();
        for (int i = tid; i < FC*NF; i += 128) {
            int ic = i >> 6, oc = i & 63;
            wslab[ic*72 + oc] = tf32_bits(g_wt[tap*(FC*NF) + i]);
        }
        __syncthreads();
        int dtr = tap / 5, dtc = tap - dtr*5;
        #pragma unroll
        for (int ks = 0; ks < 4; ks++) {
            int ic0 = ks*8;
            uint32_t a0 = wslab[(ic0+t)*72   + 16*warp + g];
            uint32_t a1 = wslab[(ic0+t)*72   + 16*warp + g + 8];
            uint32_t a2 = wslab[(ic0+t+4)*72 + 16*warp + g];
            uint32_t a3 = wslab[(ic0+t+4)*72 + 16*warp + g + 8];
            #pragma unroll
            for (int j = 0; j < 16; j++) {
                int jr = j >> 1, jc = (j & 1)*8;
                const uint32_t* bp = &tileS[((jr+dtr)*20 + jc + g + dtc)*36 + ic0 + t];
                uint32_t b0 = bp[0], b1 = bp[4];
                MMA_TF32(acc[j], a0,a1,a2,a3, b0,b1);
            }
        }
    }

    int oc0 = 16*warp + g;
    float bv0 = sbias[oc0], bv1 = sbias[oc0 + 8];
    #pragma unroll
    for (int j = 0; j < 16; j++) {
        int jr = j >> 1, jc = (j & 1)*8;
        int py = by*8 + jr;
        if (py >= HP) continue;
        int px = bx*16 + jc + 2*t;
        float* base0 = g_y3 + (((size_t)b*NF + oc0)*HP + py)*WP;
        float* base1 = g_y3 + (((size_t)b*NF + oc0 + 8)*HP + py)*WP;
        if (px < WP) {
            base0[px] = fmaxf(acc[j][0] + bv0, 0.f);
            base1[px] = fmaxf(acc[j][2] + bv1, 0.f);
        }
        if (px + 1 < WP) {
            base0[px+1] = fmaxf(acc[j][1] + bv0, 0.f);
            base1[px+1] = fmaxf(acc[j][3] + bv1, 0.f);
        }
    }
}

// ---------------- K6: conv4 3x3 pad1 (64->12) + pixel-shuffle x2 + crop + mean add
__global__ void k6_conv4(const float* __restrict__ w4, const float* __restrict__ b4,
                         float* __restrict__ out) {
    __shared__ float ws[NF*12*9];
    __shared__ float bs[12];
    __shared__ float tile[10][66];
    int b = blockIdx.z;
    int tx = threadIdx.x, ty = threadIdx.y;   // (16,8)
    int tid = ty*16 + tx;
    for (int idx = tid; idx < NF*12*9; idx += 128) {
        int ic = idx / 108; int rem = idx - ic*108;
        int o = rem / 9, t = rem - o*9;
        ws[idx] = w4[o*(NF*9) + ic*9 + t];
    }
    if (tid < 12) bs[tid] = b4[tid];
    int h  = blockIdx.y*8 + ty;
    int w0 = blockIdx.x*64 + tx*4;
    int gh0 = blockIdx.y*8 - 1;
    int gw0 = blockIdx.x*64 - 1;
    float acc[12][4];
    #pragma unroll
    for (int o = 0; o < 12; o++)
        #pragma unroll
        for (int j = 0; j < 4; j++) acc[o][j] = 0.f;
    for (int ic = 0; ic < NF; ic++) {
        __syncthreads();
        const float* src = g_y3 + (((size_t)b*NF + ic)*HP)*WP;
        for (int i = tid; i < 10*66; i += 128) {
            int r = i / 66, c2 = i - r*66;
            int hh = gh0 + r, ww = gw0 + c2;
            tile[r][c2] = (hh >= 0 && ww >= 0) ? src[hh*WP+ww] : 0.f;
        }
        __syncthreads();
        #pragma unroll
        for (int r = 0; r < 3; r++) {
            float t6[6];
            #pragma unroll
            for (int c2 = 0; c2 < 6; c2++) t6[c2] = tile[ty + r][tx*4 + c2];
            #pragma unroll
            for (int o = 0; o < 12; o++) {
                #pragma unroll
                for (int s = 0; s < 3; s++) {
                    float wv = ws[ic*108 + o*9 + r*3 + s];
                    #pragma unroll
                    for (int j = 0; j < 4; j++)
                        acc[o][j] += t6[j+s] * wv;
                }
            }
        }
    }
    #pragma unroll
    for (int o = 0; o < 12; o++) {
        int co = o >> 2, s1 = (o >> 1) & 1, s2 = o & 1;
        float mv = rgb_mean(co);
        float* dst = out + ((b*3+co)*720 + 2*h + s1)*1280;
        float bv = bs[o];
        #pragma unroll
        for (int j = 0; j < 4; j++)
            dst[2*(w0+j) + s2] = acc[o][j] + bv + mv;
    }
}

// ---------------- launch ----------------
extern "C" void kernel_launch(void* const* d_in, const int* in_sizes, int n_in,
                              void* d_out, int out_size) {
    const float* x  = (const float*)d_in[0];
    const float* w1 = (const float*)d_in[1];
    const float* b1 = (const float*)d_in[2];
    const float* w2 = (const float*)d_in[3];
    const float* b2 = (const float*)d_in[4];
    const float* wk = (const float*)d_in[5];
    const float* bk = (const float*)d_in[6];
    const float* wb = (const float*)d_in[7];
    const float* bb = (const float*)d_in[8];
    const float* w3 = (const float*)d_in[9];
    const float* b3 = (const float*)d_in[10];
    const float* w4 = (const float*)d_in[11];
    const float* b4 = (const float*)d_in[12];
    float* out = (float*)d_out;

    k5w_transpose<<<(25*FC*NF + 255)/256, 256>>>(w3);
    k2w_transpose<<<(9*FH*FH + 255)/256, 256>>>(w2);
    k1_conv1<<<BP, 256>>>(x, w1, b1);
    k2_conv2<<<BP/4, 128>>>(b2);
    k3_gemm<<<dim3(14, (BP+127)/128), 128>>>(wk, bk, wb, bb);
    k4_adapt<<<BP, 128>>>(x);
    k5_conv3<<<dim3((WP+15)/16, (HP+7)/8, B_), 128>>>(b3);
    k6_conv4<<<dim3(W_/64, H_/8, B_), dim3(16,8)>>>(w4, b4, out);
}

// round 7
// speedup vs baseline: 7.2444x; 1.3613x over previous
#include <cuda_runtime.h>
#include <cstdint>

#define B_ 4
#define C_ 3
#define H_ 360
#define W_ 640
#define HP 364
#define WP 644
#define GH 52
#define GW 92
#define BP (B_*GH*GW)   /* 19136 patches */
#define FH 64           /* F_HEAD */
#define FC 32           /* F_CH  */
#define NF 64           /* N_FEATS */

// ---------------- scratch (device globals; no allocation allowed) ----------
__device__ __align__(16) float g_feat1[BP*FH*25];   // conv1 out: [p][pos25][ic64]
__device__ __align__(16) float g_feat2[BP*FH*9];    // conv2 out: [p][oc*9+pos]
__device__ __align__(16) float g_kern [BP*FC*27];   // per-patch kernels [p][864]
__device__ __align__(16) float g_bias [BP*FC];      // per-patch bias [p][32]
__device__ __align__(16) float g_ymid [B_*FC*HP*WP];     // adaptive conv out
__device__ __align__(16) float g_y3  [(size_t)B_*NF*HP*WP]; // conv3 out
__device__ __align__(16) uint32_t g_wt [25*FC*NF];  // conv3 w tf32 [tap][ic][oc]
__device__ __align__(16) uint32_t g_wt2[9*FH*FH];   // conv2 w tf32 [tap][ic][oc]
__device__ __align__(16) uint32_t g_wt4[9*NF*16];   // conv4 w tf32 [tap][ic][oc16]

__device__ __forceinline__ float rgb_mean(int c) {
    return (c == 0) ? 0.4488f*255.0f : (c == 1) ? 0.4371f*255.0f : 0.404f*255.0f;
}

__device__ __forceinline__ uint32_t tf32_bits(float f) {
    uint32_t u;
    asm("cvt.rna.tf32.f32 %0, %1;" : "=r"(u) : "f"(f));
    return u;
}

#define MMA_TF32(ACC, A0,A1,A2,A3, B0,B1) \
    asm volatile("mma.sync.aligned.m16n8k8.row.col.f32.tf32.tf32.f32 " \
        "{%0,%1,%2,%3}, {%4,%5,%6,%7}, {%8,%9}, {%0,%1,%2,%3};\n" \
        : "+f"((ACC)[0]), "+f"((ACC)[1]), "+f"((ACC)[2]), "+f"((ACC)[3]) \
        : "r"(A0), "r"(A1), "r"(A2), "r"(A3), "r"(B0), "r"(B1))

// ---------------- weight transposes (tf32 pre-conversion) ----------------
__global__ void k5w_transpose(const float* __restrict__ w3) {
    int i = blockIdx.x*256 + threadIdx.x;
    if (i >= 25*FC*NF) return;
    int tap = i / (FC*NF);
    int rem = i - tap*(FC*NF);
    int ic = rem >> 6, oc = rem & 63;
    g_wt[i] = tf32_bits(w3[(oc*FC + ic)*25 + tap]);
}
__global__ void k2w_transpose(const float* __restrict__ w2) {
    int i = blockIdx.x*256 + threadIdx.x;
    if (i >= 9*FH*FH) return;
    int tap = i / (FH*FH);
    int rem = i - tap*(FH*FH);
    int ic = rem >> 6, oc = rem & 63;
    g_wt2[i] = tf32_bits(w2[(oc*FH + ic)*9 + tap]);
}
__global__ void k6w_transpose(const float* __restrict__ w4) {
    int i = blockIdx.x*256 + threadIdx.x;
    if (i >= 9*NF*16) return;
    int tap = i / (NF*16);
    int rem = i - tap*(NF*16);
    int ic = rem >> 4, oc = rem & 15;
    float v = (oc < 12) ? w4[(oc*NF + ic)*9 + tap] : 0.f;
    g_wt4[i] = tf32_bits(v);
}

// ---------------- K1: patch extract + conv1 3x3 VALID + relu
__global__ void k1_conv1(const float* __restrict__ x, const float* __restrict__ w1,
                         const float* __restrict__ b1) {
    __shared__ float sp[C_*49];
    __shared__ float ws[FH*27];
    __shared__ float bs[FH];
    int p = blockIdx.x;
    int b = p / (GH*GW);
    int r = p % (GH*GW);
    int gi = r / GW, gj = r % GW;
    int tid = threadIdx.x;
    if (tid < C_*49) {
        int c = tid/49, q = tid%49;
        int i = q/7, j = q%7;
        int h = gi*7 + i, w = gj*7 + j;
        float v = 0.f;
        if (h < H_ && w < W_) v = x[((b*C_+c)*H_ + h)*W_ + w] - rgb_mean(c);
        sp[tid] = v;
    }
    for (int idx = tid; idx < FH*27; idx += blockDim.x) ws[idx] = w1[idx];
    if (tid < FH) bs[tid] = b1[tid];
    __syncthreads();
    for (int idx = tid; idx < FH*25; idx += blockDim.x) {
        int q = idx >> 6, oc = idx & 63;   // pos-major, ic contiguous
        int oy = q/5, ox = q%5;
        float acc = bs[oc];
        #pragma unroll
        for (int c = 0; c < 3; c++)
            #pragma unroll
            for (int ky = 0; ky < 3; ky++)
                #pragma unroll
                for (int kx = 0; kx < 3; kx++)
                    acc += sp[c*49 + (oy+ky)*7 + (ox+kx)] * ws[oc*27 + c*9 + ky*3 + kx];
        g_feat1[(size_t)p*(FH*25) + idx] = fmaxf(acc, 0.f);
    }
}

// ---------------- K2: conv2 3x3 VALID (64->64) + relu — tf32 mma implicit GEMM.
__global__ void __launch_bounds__(128) k2_conv2(const float* __restrict__ b2) {
    __shared__ __align__(16) uint32_t sf[4*25*68];    // [pl*25+pos][ic pad 68]
    __shared__ __align__(16) uint32_t wslab[64*72];   // [ic][oc pad 72]
    int tid = threadIdx.x;
    int p0 = blockIdx.x*4;
    int warp = tid >> 5, lane = tid & 31;
    int g = lane >> 2, t = lane & 3;

    for (int i = tid; i < 4*400; i += 128) {
        int pl = i / 400, rem = i - pl*400;
        int pos = rem >> 4, c = rem & 15;
        float4 v = *(const float4*)&g_feat1[(size_t)(p0+pl)*1600 + pos*64 + 4*c];
        uint32_t* dst = &sf[(pl*25+pos)*68 + 4*c];
        dst[0]=tf32_bits(v.x); dst[1]=tf32_bits(v.y);
        dst[2]=tf32_bits(v.z); dst[3]=tf32_bits(v.w);
    }

    int rB[5];
    #pragma unroll
    for (int j = 0; j < 5; j++) {
        int col = 8*j + g;
        int cc = (col < 36) ? col : 35;
        int pl = cc/9, pos = cc - pl*9;
        int oy = pos/3, ox = pos - oy*3;
        rB[j] = pl*25 + oy*5 + ox;
    }
    float acc[5][4];
    #pragma unroll
    for (int j = 0; j < 5; j++)
        #pragma unroll
        for (int q = 0; q < 4; q++) acc[j][q] = 0.f;

    for (int tap = 0; tap < 9; tap++) {
        __syncthreads();
        #pragma unroll
        for (int i = tid; i < 1024; i += 128) {   // uint4 copy, preconverted
            int ic = i >> 4, c = i & 15;
            *(uint4*)&wslab[ic*72 + 4*c] = *(const uint4*)&g_wt2[tap*4096 + ic*64 + 4*c];
        }
        __syncthreads();
        int dtr = tap/3, dtc = tap - dtr*3;
        int roff = (dtr*5 + dtc)*68;
        #pragma unroll
        for (int ks = 0; ks < 8; ks++) {
            int kl = ks*8;
            uint32_t a0 = wslab[(kl+t)*72   + 16*warp + g];
            uint32_t a1 = wslab[(kl+t)*72   + 16*warp + g + 8];
            uint32_t a2 = wslab[(kl+t+4)*72 + 16*warp + g];
            uint32_t a3 = wslab[(kl+t+4)*72 + 16*warp + g + 8];
            #pragma unroll
            for (int j = 0; j < 5; j++) {
                const uint32_t* bp = &sf[rB[j]*68 + roff + kl + t];
                uint32_t b0 = bp[0], b1 = bp[4];
                MMA_TF32(acc[j], a0,a1,a2,a3, b0,b1);
            }
        }
    }

    int oc0 = 16*warp + g;
    float bv0 = b2[oc0], bv1 = b2[oc0+8];
    #pragma unroll
    for (int j = 0; j < 5; j++) {
        #pragma unroll
        for (int h2 = 0; h2 < 2; h2++) {
            int col = 8*j + 2*t + h2;
            if (col >= 36) continue;
            int pl = col/9, pos = col - pl*9;
            float* d = g_feat2 + (size_t)(p0+pl)*576;
            d[oc0*9 + pos]     = fmaxf(acc[j][h2]   + bv0, 0.f);
            d[(oc0+8)*9 + pos] = fmaxf(acc[j][2+h2] + bv1, 0.f);
        }
    }
}

// ---------------- K3: fused GEMM C[BP][896] = feat2[BP][576] x [wk;wb]^T + [bk;bb]
__global__ void __launch_bounds__(128) k3_gemm(const float* __restrict__ wk,
                                               const float* __restrict__ bk,
                                               const float* __restrict__ wb,
                                               const float* __restrict__ bb) {
    __shared__ uint32_t As[128*36];
    __shared__ uint32_t Bs[64*36];
    int tid = threadIdx.x;
    int warp = tid >> 5, lane = tid & 31;
    int g = lane >> 2, t = lane & 3;
    int m0 = blockIdx.y*128, n0 = blockIdx.x*64;
    int c = tid & 7, r0 = tid >> 3;

    float acc[2][8][4];
    #pragma unroll
    for (int mt = 0; mt < 2; mt++)
        #pragma unroll
        for (int j = 0; j < 8; j++)
            #pragma unroll
            for (int q = 0; q < 4; q++) acc[mt][j][q] = 0.f;

    for (int k0 = 0; k0 < 576; k0 += 32) {
        __syncthreads();
        #pragma unroll
        for (int rr = r0; rr < 128; rr += 16) {
            int m = m0 + rr;
            float4 v = make_float4(0.f,0.f,0.f,0.f);
            if (m < BP) v = *(const float4*)&g_feat2[(size_t)m*576 + k0 + 4*c];
            uint32_t* dst = &As[rr*36 + 4*c];
            dst[0]=tf32_bits(v.x); dst[1]=tf32_bits(v.y);
            dst[2]=tf32_bits(v.z); dst[3]=tf32_bits(v.w);
        }
        #pragma unroll
        for (int rr = r0; rr < 64; rr += 16) {
            int n = n0 + rr;
            const float* src = (n < 864) ? &wk[(size_t)n*576] : &wb[(size_t)(n-864)*576];
            float4 v = *(const float4*)&src[k0 + 4*c];
            uint32_t* dst = &Bs[rr*36 + 4*c];
            dst[0]=tf32_bits(v.x); dst[1]=tf32_bits(v.y);
            dst[2]=tf32_bits(v.z); dst[3]=tf32_bits(v.w);
        }
        __syncthreads();
        #pragma unroll
        for (int ks = 0; ks < 4; ks++) {
            int kl = ks*8;
            uint32_t bf[8][2];
            #pragma unroll
            for (int j = 0; j < 8; j++) {
                bf[j][0] = Bs[(8*j+g)*36 + kl + t];
                bf[j][1] = Bs[(8*j+g)*36 + kl + t + 4];
            }
            #pragma unroll
            for (int mt = 0; mt < 2; mt++) {
                int mb = 32*warp + 16*mt;
                uint32_t a0 = As[(mb+g)*36   + kl + t];
                uint32_t a1 = As[(mb+g+8)*36 + kl + t];
                uint32_t a2 = As[(mb+g)*36   + kl + t + 4];
                uint32_t a3 = As[(mb+g+8)*36 + kl + t + 4];
                #pragma unroll
                for (int j = 0; j < 8; j++)
                    MMA_TF32(acc[mt][j], a0,a1,a2,a3, bf[j][0], bf[j][1]);
            }
        }
    }

    #pragma unroll
    for (int mt = 0; mt < 2; mt++) {
        int m = m0 + 32*warp + 16*mt + g;
        #pragma unroll
        for (int j = 0; j < 8; j++) {
            #pragma unroll
            for (int h2 = 0; h2 < 2; h2++) {
                int n = n0 + 8*j + 2*t + h2;
                float v0 = acc[mt][j][h2], v1 = acc[mt][j][2+h2];
                if (n < 864) {
                    float bv = bk[n];
                    if (m < BP)     g_kern[(size_t)m*864 + n]     = v0 + bv;
                    if (m+8 < BP)   g_kern[(size_t)(m+8)*864 + n] = v1 + bv;
                } else {
                    float bv = bb[n-864];
                    if (m < BP)     g_bias[(size_t)m*32 + (n-864)]     = v0 + bv;
                    if (m+8 < BP)   g_bias[(size_t)(m+8)*32 + (n-864)] = v1 + bv;
                }
            }
        }
    }
}

// ---------------- K4: adaptive per-patch 3x3 conv
__global__ void k4_adapt(const float* __restrict__ x) {
    __shared__ float ks[FC*27];
    __shared__ float bs[FC];
    __shared__ float xs[C_*81];
    int p = blockIdx.x;
    int b = p/(GH*GW); int r = p%(GH*GW);
    int gi = r/GW, gj = r%GW;
    int tid = threadIdx.x;  // 128
    for (int idx = tid; idx < FC*27; idx += blockDim.x) ks[idx] = g_kern[(size_t)p*(FC*27)+idx];
    if (tid < FC) bs[tid] = g_bias[(size_t)p*FC+tid];
    for (int idx = tid; idx < C_*81; idx += blockDim.x) xs[idx] = 0.f;
    __syncthreads();
    for (int idx = tid; idx < C_*49; idx += blockDim.x) {
        int c = idx/49, q = idx%49, i = q/7, j = q%7;
        int h = gi*7+i, w = gj*7+j;
        float v = 0.f;
        if (h < H_ && w < W_) v = x[((b*C_+c)*H_+h)*W_+w] - rgb_mean(c);
        xs[c*81 + (i+1)*9 + (j+1)] = v;
    }
    __syncthreads();
    if (tid < 49) {
        int i = tid/7, j = tid%7;
        float v[27];
        #pragma unroll
        for (int c = 0; c < 3; c++)
            #pragma unroll
            for (int di = 0; di < 3; di++)
                #pragma unroll
                for (int dj = 0; dj < 3; dj++)
                    v[c*9+di*3+dj] = xs[c*81 + (i+di)*9 + (j+dj)];
        int h = gi*7+i, w = gj*7+j;
        for (int f = 0; f < FC; f++) {
            float acc = bs[f];
            #pragma unroll
            for (int k = 0; k < 27; k++) acc += ks[f*27+k]*v[k];
            g_ymid[((b*FC+f)*HP + h)*WP + w] = acc;
        }
    }
}

// ---------------- K5: conv3 5x5 pad2, 32->64, relu — tf32 mma implicit GEMM.
__global__ void __launch_bounds__(128) k5_conv3(const float* __restrict__ b3) {
    __shared__ __align__(16) uint32_t tileS[12*20*36];
    __shared__ __align__(16) uint32_t wslab[32*72];
    __shared__ float sbias[NF];
    int b  = blockIdx.z;
    int by = blockIdx.y, bx = blockIdx.x;
    int tid = threadIdx.x;
    int warp = tid >> 5, lane = tid & 31;
    int g = lane >> 2, t = lane & 3;
    int gh0 = by*8 - 2, gw0 = bx*16 - 2;

    for (int i = tid; i < FC*240; i += 128) {
        int ic = i / 240, pos = i - ic*240;
        int r = pos / 20, c = pos - r*20;
        int hh = gh0 + r, ww = gw0 + c;
        float v = 0.f;
        if (hh >= 0 && hh < HP && ww >= 0 && ww < WP)
            v = g_ymid[((b*FC + ic)*HP + hh)*WP + ww];
        tileS[(r*20 + c)*36 + ic] = tf32_bits(v);
    }
    if (tid < NF) sbias[tid] = b3[tid];

    float acc[16][4];
    #pragma unroll
    for (int j = 0; j < 16; j++)
        #pragma unroll
        for (int q = 0; q < 4; q++) acc[j][q] = 0.f;

    for (int tap = 0; tap < 25; tap++) {
        __syncthreads();
        #pragma unroll
        for (int i = tid; i < 512; i += 128) {   // uint4 copy, preconverted
            int ic = i >> 4, c = i & 15;
            *(uint4*)&wslab[ic*72 + 4*c] = *(const uint4*)&g_wt[tap*2048 + ic*64 + 4*c];
        }
        __syncthreads();
        int dtr = tap / 5, dtc = tap - dtr*5;
        #pragma unroll
        for (int ks = 0; ks < 4; ks++) {
            int ic0 = ks*8;
            uint32_t a0 = wslab[(ic0+t)*72   + 16*warp + g];
            uint32_t a1 = wslab[(ic0+t)*72   + 16*warp + g + 8];
            uint32_t a2 = wslab[(ic0+t+4)*72 + 16*warp + g];
            uint32_t a3 = wslab[(ic0+t+4)*72 + 16*warp + g + 8];
            #pragma unroll
            for (int j = 0; j < 16; j++) {
                int jr = j >> 1, jc = (j & 1)*8;
                const uint32_t* bp = &tileS[((jr+dtr)*20 + jc + g + dtc)*36 + ic0 + t];
                uint32_t b0 = bp[0], b1 = bp[4];
                MMA_TF32(acc[j], a0,a1,a2,a3, b0,b1);
            }
        }
    }

    int oc0 = 16*warp + g;
    float bv0 = sbias[oc0], bv1 = sbias[oc0 + 8];
    #pragma unroll
    for (int j = 0; j < 16; j++) {
        int jr = j >> 1, jc = (j & 1)*8;
        int py = by*8 + jr;
        if (py >= HP) continue;
        int px = bx*16 + jc + 2*t;
        float* base0 = g_y3 + (((size_t)b*NF + oc0)*HP + py)*WP;
        float* base1 = g_y3 + (((size_t)b*NF + oc0 + 8)*HP + py)*WP;
        if (px < WP) {
            base0[px] = fmaxf(acc[j][0] + bv0, 0.f);
            base1[px] = fmaxf(acc[j][2] + bv1, 0.f);
        }
        if (px + 1 < WP) {
            base0[px+1] = fmaxf(acc[j][1] + bv0, 0.f);
            base1[px+1] = fmaxf(acc[j][3] + bv1, 0.f);
        }
    }
}

// ---------------- K6: conv4 3x3 pad1 (64->12) + pixel-shuffle — tf32 mma.
// Block 128 thr (4 warps). M=16 (12 oc + 4 pad), N=128 px (8 rows x 16 cols),
// K = 2 ic-halves x 9 taps x 32 ic. Tile [10x18][ic32 pad 36] (25.9 KB),
// weight slab [32][oc pad 24] (3 KB; stride 24 -> t*24+g bank-bijective).
__global__ void __launch_bounds__(128) k6_conv4(const float* __restrict__ b4,
                                                float* __restrict__ out) {
    __shared__ __align__(16) uint32_t tileS[180*36];   // 25.9 KB
    __shared__ __align__(16) uint32_t wslab[32*24];    //  3 KB
    __shared__ float sbias[16];
    int b  = blockIdx.z;
    int by = blockIdx.y, bx = blockIdx.x;
    int tid = threadIdx.x;
    int warp = tid >> 5, lane = tid & 31;
    int g = lane >> 2, t = lane & 3;
    int gh0 = by*8 - 1, gw0 = bx*16 - 1;
    if (tid < 16) sbias[tid] = (tid < 12) ? b4[tid] : 0.f;

    float acc[4][4];
    #pragma unroll
    for (int j = 0; j < 4; j++)
        #pragma unroll
        for (int q = 0; q < 4; q++) acc[j][q] = 0.f;

    for (int half = 0; half < 2; half++) {
        int icg = half*32;
        __syncthreads();   // WAR on tileS
        for (int i = tid; i < 32*180; i += 128) {
            int icl = i / 180, pos = i - icl*180;
            int r = pos / 18, c = pos - r*18;
            int hh = gh0 + r, ww = gw0 + c;
            float v = 0.f;
            if (hh >= 0 && ww >= 0)   // hh<=360<HP, ww<=639+? <WP always
                v = g_y3[(((size_t)b*NF + icg + icl)*HP + hh)*WP + ww];
            tileS[pos*36 + icl] = tf32_bits(v);
        }
        for (int tap = 0; tap < 9; tap++) {
            __syncthreads();   // WAR on wslab (first iter also covers tileS)
            {   // 512 uint32 = 128 uint4, one per thread
                int icl = tid >> 2, c = tid & 3;
                *(uint4*)&wslab[icl*24 + 4*c] =
                    *(const uint4*)&g_wt4[tap*(NF*16) + (icg+icl)*16 + 4*c];
            }
            __syncthreads();
            int dtr = tap/3, dtc = tap - dtr*3;
            #pragma unroll
            for (int ks = 0; ks < 4; ks++) {
                int kl = ks*8;
                uint32_t a0 = wslab[(kl+t)*24   + g];
                uint32_t a1 = wslab[(kl+t)*24   + g + 8];
                uint32_t a2 = wslab[(kl+t+4)*24 + g];
                uint32_t a3 = wslab[(kl+t+4)*24 + g + 8];
                #pragma unroll
                for (int jj = 0; jj < 4; jj++) {
                    int jn = warp*4 + jj;
                    int jr = jn >> 1, jc = (jn & 1)*8;
                    const uint32_t* bp = &tileS[((jr+dtr)*18 + jc + g + dtc)*36 + kl + t];
                    uint32_t b0 = bp[0], b1 = bp[4];
                    MMA_TF32(acc[jj], a0,a1,a2,a3, b0,b1);
                }
            }
        }
    }

    // epilogue: m rows g (acc[0,1]) and g+8 (acc[2,3]); pixel-shuffle + mean
    #pragma unroll
    for (int jj = 0; jj < 4; jj++) {
        int jn = warp*4 + jj;
        int jr = jn >> 1, jc = (jn & 1)*8;
        int h = by*8 + jr;            // < 360
        int px = bx*16 + jc + 2*t;    // < 640
        #pragma unroll
        for (int mrow = 0; mrow < 2; mrow++) {
            int o = g + 8*mrow;
            if (o >= 12) continue;
            int co = o >> 2, s1 = (o >> 1) & 1, s2 = o & 1;
            float bv = sbias[o] + rgb_mean(co);
            float* dst = out + ((b*3+co)*720 + 2*h + s1)*1280;
            dst[2*px + s2]     = acc[jj][2*mrow]   + bv;
            dst[2*(px+1) + s2] = acc[jj][2*mrow+1] + bv;
        }
    }
}

// ---------------- launch ----------------
extern "C" void kernel_launch(void* const* d_in, const int* in_sizes, int n_in,
                              void* d_out, int out_size) {
    const float* x  = (const float*)d_in[0];
    const float* w1 = (const float*)d_in[1];
    const float* b1 = (const float*)d_in[2];
    const float* w2 = (const float*)d_in[3];
    const float* b2 = (const float*)d_in[4];
    const float* wk = (const float*)d_in[5];
    const float* bk = (const float*)d_in[6];
    const float* wb = (const float*)d_in[7];
    const float* bb = (const float*)d_in[8];
    const float* w3 = (const float*)d_in[9];
    const float* b3 = (const float*)d_in[10];
    const float* w4 = (const float*)d_in[11];
    const float* b4 = (const float*)d_in[12];
    float* out = (float*)d_out;

    k5w_transpose<<<(25*FC*NF + 255)/256, 256>>>(w3);
    k2w_transpose<<<(9*FH*FH + 255)/256, 256>>>(w2);
    k6w_transpose<<<(9*NF*16 + 255)/256, 256>>>(w4);
    k1_conv1<<<BP, 256>>>(x, w1, b1);
    k2_conv2<<<BP/4, 128>>>(b2);
    k3_gemm<<<dim3(14, (BP+127)/128), 128>>>(wk, bk, wb, bb);
    k4_adapt<<<BP, 128>>>(x);
    k5_conv3<<<dim3((WP+15)/16, (HP+7)/8, B_), 128>>>(b3);
    k6_conv4<<<dim3(W_/16, H_/8, B_), 128>>>(b4, out);
}